// round 3
// baseline (speedup 1.0000x reference)
#include <cuda_runtime.h>
#include <cstdint>

#define NMAX 50000
#define EMAX 800000
#define GNUM 512
#define HID 64
#define LAY 5
#define HL 320
#define BN_EPS 1e-5f

// ---------------- static scratch ----------------
__device__ float g_z   [(size_t)NMAX * HID];
__device__ float g_outs[(size_t)NMAX * HL];    // RAW gemm2 outputs per layer (pre-BN), col l*64
__device__ float g_stats[LAY * 256];           // per layer: sum(z),sq(z),sum(v),sq(v)
__device__ int   g_starts[GNUM + 1];
__device__ int   g_is64_e, g_is64_b;
// CSR
__device__ int   g_deg[NMAX];
__device__ int   g_rowptr[NMAX + 1];
__device__ int   g_cur[NMAX];
__device__ int   g_part[256];
__device__ int   g_partscan[256];
__device__ int   g_csrc[EMAX];

__device__ __forceinline__ long ldidx(const void* p, long i, int is64) {
    return is64 ? (long)((const long long*)p)[i] : (long)((const int*)p)[i];
}

// ---------------- dtype detection ----------------
__global__ void detect_kernel(const void* ei, const void* batch, int ncount) {
    __shared__ int flag;
    const int* p = (const int*)ei;
    if (threadIdx.x == 0) flag = 0;
    __syncthreads();
    for (int i = threadIdx.x; i < 4096; i += blockDim.x)
        if (p[2 * i + 1] != 0) atomicOr(&flag, 1);
    __syncthreads();
    if (threadIdx.x == 0) { g_is64_e = (flag == 0); flag = 0; }
    __syncthreads();
    const int* q = (const int*)batch;
    int half = ncount / 2;
    for (int i = threadIdx.x; i < 2048; i += blockDim.x) {
        int pos = half - 1 - i;
        if (pos >= 0 && q[2 * pos + 1] != 0) atomicOr(&flag, 1);
    }
    __syncthreads();
    if (threadIdx.x == 0) g_is64_b = (flag == 0);
}

// ---------------- CSR build ----------------
__global__ void zero_kernel(int n) {
    int i = blockIdx.x * blockDim.x + threadIdx.x;
    if (i < n) g_deg[i] = 0;
    if (i < LAY * 256) g_stats[i] = 0.f;
}

__global__ void hist_kernel(const void* __restrict__ ei, int E) {
    int e = blockIdx.x * blockDim.x + threadIdx.x;
    if (e >= E) return;
    int dst = (int)ldidx(ei, (long)E + e, g_is64_e);
    atomicAdd(&g_deg[dst], 1);
}

__global__ void scan1_kernel(int n) {
    __shared__ int sh[256];
    int i = blockIdx.x * 256 + threadIdx.x;
    int v = (i < n) ? g_deg[i] : 0;
    sh[threadIdx.x] = v;
    __syncthreads();
    for (int off = 128; off > 0; off >>= 1) {
        if (threadIdx.x < off) sh[threadIdx.x] += sh[threadIdx.x + off];
        __syncthreads();
    }
    if (threadIdx.x == 0) g_part[blockIdx.x] = sh[0];
}

__global__ void scan2_kernel(int nblocks) {
    __shared__ int sh[256];
    int t = threadIdx.x;
    int v = (t < nblocks) ? g_part[t] : 0;
    sh[t] = v;
    __syncthreads();
    for (int off = 1; off < 256; off <<= 1) {
        int x = (t >= off) ? sh[t - off] : 0;
        __syncthreads();
        sh[t] += x;
        __syncthreads();
    }
    if (t < nblocks) g_partscan[t] = sh[t] - v;
}

__global__ void scan3_kernel(int n, int E) {
    __shared__ int sh[256];
    int t = threadIdx.x;
    int i = blockIdx.x * 256 + t;
    int v = (i < n) ? g_deg[i] : 0;
    sh[t] = v;
    __syncthreads();
    for (int off = 1; off < 256; off <<= 1) {
        int x = (t >= off) ? sh[t - off] : 0;
        __syncthreads();
        sh[t] += x;
        __syncthreads();
    }
    if (i < n) {
        int rp = g_partscan[blockIdx.x] + sh[t] - v;
        g_rowptr[i] = rp;
        g_cur[i] = rp;
        if (i == n - 1) g_rowptr[n] = E;
    }
}

__global__ void fill_kernel(const void* __restrict__ ei, int E) {
    int e = blockIdx.x * blockDim.x + threadIdx.x;
    if (e >= E) return;
    int is64 = g_is64_e;
    int src = (int)ldidx(ei, e, is64);
    int dst = (int)ldidx(ei, (long)E + e, is64);
    int pos = atomicAdd(&g_cur[dst], 1);
    g_csrc[pos] = src;
}

// ---------------- layer 0: fused agg + outer-product GEMM + stats ----------------
// block = 256 threads, covers 64 rows
__global__ __launch_bounds__(256) void l0_kernel(
    const float* __restrict__ x, const float* __restrict__ w,
    const float* __restrict__ bias, int n)
{
    __shared__ float s_x[64];
    int t = threadIdx.x;
    int lane = t & 31, warp = t >> 5;
    int r0 = blockIdx.x * 64;

    // phase A: 8 warps x 8 rows, lanes parallel over neighbors
    for (int rr = 0; rr < 8; rr++) {
        int rl = warp * 8 + rr;
        int row = r0 + rl;
        float acc = 0.f;
        if (row < n) {
            int beg = g_rowptr[row], end = g_rowptr[row + 1];
            for (int base = beg + lane; base < end; base += 32)
                acc += x[g_csrc[base]];
        }
        #pragma unroll
        for (int o = 16; o > 0; o >>= 1)
            acc += __shfl_xor_sync(0xFFFFFFFFu, acc, o);
        if (lane == 0)
            s_x[rl] = (row < n) ? (acc + x[row]) : 0.f;
    }
    __syncthreads();

    // phase B: 4 groups x 64 channels; each group does 16 rows
    int c = t & 63, g = t >> 6;
    float wc = w[c], bc = bias[c];
    float s = 0.f, q = 0.f;
    int i0 = g * 16;
    #pragma unroll
    for (int i = 0; i < 16; i++) {
        int row = r0 + i0 + i;
        if (row < n) {
            float zv = s_x[i0 + i] * wc + bc;
            g_z[(size_t)row * HID + c] = zv;
            s += zv; q += zv * zv;
        }
    }
    atomicAdd(&g_stats[c], s);
    atomicAdd(&g_stats[64 + c], q);
}

// ---------------- gemm1 (layers 1..4): fused gather + normalize + GEMM + stats ----
// input: raw prev-layer v in g_outs col (l-1)*64, normalized via prev stats/go/bo
__global__ __launch_bounds__(256) void gemm1agg_kernel(
    int l, const float* __restrict__ w, const float* __restrict__ bias,
    const float* __restrict__ go, const float* __restrict__ bo,
    int n, float invN)
{
    __shared__ float s_in[64][65];
    __shared__ float s_w[64][64];
    __shared__ float s_a[64], s_b[64];
    int t = threadIdx.x;
    int lane = t & 31, warp = t >> 5;
    int r0 = blockIdx.x * 64;
    int pc = (l - 1) * HID;
    int pso = (l - 1) * 256 + 128;   // prev-layer v stats

    // phase 0: prev-layer BN coefs
    if (t < 64) {
        float mean = g_stats[pso + t] * invN;
        float var  = g_stats[pso + 64 + t] * invN - mean * mean;
        float a = go[pc + t] * rsqrtf(var + BN_EPS);
        s_a[t] = a;
        s_b[t] = bo[pc + t] - mean * a;
    }
    // weights
    for (int idx = t; idx < 4096; idx += 256)
        s_w[idx >> 6][idx & 63] = w[idx];
    __syncthreads();

    // phase 1: gather. 8 warps x 8 rows; lane covers channels lane*2, lane*2+1
    float a0 = s_a[lane * 2], b0 = s_b[lane * 2];
    float a1 = s_a[lane * 2 + 1], b1 = s_b[lane * 2 + 1];
    for (int rr = 0; rr < 8; rr++) {
        int rl = warp * 8 + rr;
        int row = r0 + rl;
        float v0 = 0.f, v1 = 0.f;
        if (row < n) {
            int beg = g_rowptr[row], end = g_rowptr[row + 1];
            for (int base = beg; base < end; base += 32) {
                int cnt = min(32, end - base);
                int idx = 0;
                if (lane < cnt) idx = g_csrc[base + lane];
                for (int jj = 0; jj < cnt; jj++) {
                    int src = __shfl_sync(0xFFFFFFFFu, idx, jj);
                    float2 raw = *(const float2*)(g_outs + (size_t)src * HL + pc + lane * 2);
                    v0 += fmaxf(fmaf(raw.x, a0, b0), 0.f);
                    v1 += fmaxf(fmaf(raw.y, a1, b1), 0.f);
                }
            }
            // own h term
            float2 hw = *(const float2*)(g_outs + (size_t)row * HL + pc + lane * 2);
            v0 += fmaxf(fmaf(hw.x, a0, b0), 0.f);
            v1 += fmaxf(fmaf(hw.y, a1, b1), 0.f);
        }
        s_in[rl][lane * 2]     = v0;
        s_in[rl][lane * 2 + 1] = v1;
    }
    __syncthreads();

    // phase 2: 64x64 GEMM, 16 outputs/thread
    int r = t & 63, cg = t >> 6, c0 = cg * 16;
    float acc[16];
    #pragma unroll
    for (int j = 0; j < 16; j++) acc[j] = bias[c0 + j];
    #pragma unroll
    for (int k = 0; k < 64; k++) {
        float a = s_in[r][k];
        const float4* wrow = (const float4*)&s_w[k][c0];
        #pragma unroll
        for (int m = 0; m < 4; m++) {
            float4 wv = wrow[m];
            acc[4*m+0] = fmaf(a, wv.x, acc[4*m+0]);
            acc[4*m+1] = fmaf(a, wv.y, acc[4*m+1]);
            acc[4*m+2] = fmaf(a, wv.z, acc[4*m+2]);
            acc[4*m+3] = fmaf(a, wv.w, acc[4*m+3]);
        }
    }
    int gr = r0 + r;
    bool valid = gr < n;
    if (valid) {
        float4* op = (float4*)&g_z[(size_t)gr * HID + c0];
        #pragma unroll
        for (int m = 0; m < 4; m++)
            op[m] = make_float4(acc[4*m], acc[4*m+1], acc[4*m+2], acc[4*m+3]);
    }
    int so = l * 256;
    #pragma unroll
    for (int j = 0; j < 16; j++) {
        float s = valid ? acc[j] : 0.f;
        float q = s * s;
        #pragma unroll
        for (int o = 16; o > 0; o >>= 1) {
            s += __shfl_down_sync(0xFFFFFFFFu, s, o);
            q += __shfl_down_sync(0xFFFFFFFFu, q, o);
        }
        if ((t & 31) == 0) {
            atomicAdd(&g_stats[so + c0 + j], s);
            atomicAdd(&g_stats[so + 64 + c0 + j], q);
        }
    }
}

// ---------------- gemm2: inline coef1 + GEMM + stats, writes raw v to g_outs ----
__global__ __launch_bounds__(256) void gemm2_kernel(
    int l, const float* __restrict__ w, const float* __restrict__ bias,
    const float* __restrict__ gm, const float* __restrict__ bm,
    int n, float invN)
{
    __shared__ float s_in[64][65];
    __shared__ float s_w[64][64];
    __shared__ float s_a[64], s_b[64];
    int t = threadIdx.x;
    int zso = l * 256;

    if (t < 64) {
        float mean = g_stats[zso + t] * invN;
        float var  = g_stats[zso + 64 + t] * invN - mean * mean;
        float a = gm[l * HID + t] * rsqrtf(var + BN_EPS);
        s_a[t] = a;
        s_b[t] = bm[l * HID + t] - mean * a;
    }
    for (int idx = t; idx < 4096; idx += 256)
        s_w[idx >> 6][idx & 63] = w[idx];
    __syncthreads();

    int r0 = blockIdx.x * 64;
    // load z, apply relu(BN) inline; float4 per thread
    for (int idx = t; idx < 1024; idx += 256) {
        int r = idx >> 4, k4 = idx & 15;
        int gr = r0 + r;
        float4 val = make_float4(0.f, 0.f, 0.f, 0.f);
        if (gr < n) {
            float4 z = *(const float4*)(g_z + (size_t)gr * HID + k4 * 4);
            val.x = fmaxf(fmaf(z.x, s_a[k4*4+0], s_b[k4*4+0]), 0.f);
            val.y = fmaxf(fmaf(z.y, s_a[k4*4+1], s_b[k4*4+1]), 0.f);
            val.z = fmaxf(fmaf(z.z, s_a[k4*4+2], s_b[k4*4+2]), 0.f);
            val.w = fmaxf(fmaf(z.w, s_a[k4*4+3], s_b[k4*4+3]), 0.f);
        }
        s_in[r][k4*4+0] = val.x;
        s_in[r][k4*4+1] = val.y;
        s_in[r][k4*4+2] = val.z;
        s_in[r][k4*4+3] = val.w;
    }
    __syncthreads();

    int r = t & 63, cg = t >> 6, c0 = cg * 16;
    float acc[16];
    #pragma unroll
    for (int j = 0; j < 16; j++) acc[j] = bias[c0 + j];
    #pragma unroll
    for (int k = 0; k < 64; k++) {
        float a = s_in[r][k];
        const float4* wrow = (const float4*)&s_w[k][c0];
        #pragma unroll
        for (int m = 0; m < 4; m++) {
            float4 wv = wrow[m];
            acc[4*m+0] = fmaf(a, wv.x, acc[4*m+0]);
            acc[4*m+1] = fmaf(a, wv.y, acc[4*m+1]);
            acc[4*m+2] = fmaf(a, wv.z, acc[4*m+2]);
            acc[4*m+3] = fmaf(a, wv.w, acc[4*m+3]);
        }
    }
    int gr = r0 + r;
    bool valid = gr < n;
    if (valid) {
        float4* op = (float4*)(g_outs + (size_t)gr * HL + l * HID + c0);
        #pragma unroll
        for (int m = 0; m < 4; m++)
            op[m] = make_float4(acc[4*m], acc[4*m+1], acc[4*m+2], acc[4*m+3]);
    }
    int vso = l * 256 + 128;
    #pragma unroll
    for (int j = 0; j < 16; j++) {
        float s = valid ? acc[j] : 0.f;
        float q = s * s;
        #pragma unroll
        for (int o = 16; o > 0; o >>= 1) {
            s += __shfl_down_sync(0xFFFFFFFFu, s, o);
            q += __shfl_down_sync(0xFFFFFFFFu, q, o);
        }
        if ((t & 31) == 0) {
            atomicAdd(&g_stats[vso + c0 + j], s);
            atomicAdd(&g_stats[vso + 64 + c0 + j], q);
        }
    }
}

// ---------------- pooling ----------------
__global__ void starts_kernel(const void* __restrict__ batch, int n) {
    int i = blockIdx.x * blockDim.x + threadIdx.x;
    if (i >= n) return;
    int is64 = g_is64_b;
    int bi = (int)ldidx(batch, i, is64);
    int bp = (i == 0) ? -1 : (int)ldidx(batch, i - 1, is64);
    for (int g = bp + 1; g <= bi; g++) g_starts[g] = i;
    if (i == n - 1)
        for (int g = bi + 1; g <= GNUM; g++) g_starts[g] = n;
}

// pool: apply per-layer relu(BN) on the fly, sum per graph, classify
__global__ void pool_kernel(const float* __restrict__ x, const float* __restrict__ lin_w,
                            const float* __restrict__ lin_b,
                            const float* __restrict__ go, const float* __restrict__ bo,
                            float* __restrict__ out, float invN)
{
    __shared__ float s_a[HL], s_b[HL];
    __shared__ float sd[HL + 1];
    int g = blockIdx.x;
    for (int c = threadIdx.x; c < HL; c += blockDim.x) {
        int l = c >> 6, ch = c & 63;
        int vso = l * 256 + 128;
        float mean = g_stats[vso + ch] * invN;
        float var  = g_stats[vso + 64 + ch] * invN - mean * mean;
        float a = go[c] * rsqrtf(var + BN_EPS);
        s_a[c] = a;
        s_b[c] = bo[c] - mean * a;
    }
    __syncthreads();
    int s = g_starts[g], e = g_starts[g + 1];
    for (int c = threadIdx.x; c < HL + 1; c += blockDim.x) {
        float acc = 0.f;
        if (c == 0) {
            for (int r = s; r < e; r++) acc += x[r];
        } else {
            float a = s_a[c - 1], b = s_b[c - 1];
            for (int r = s; r < e; r++)
                acc += fmaxf(fmaf(g_outs[(size_t)r * HL + (c - 1)], a, b), 0.f);
        }
        sd[c] = acc;
    }
    __syncthreads();
    if (threadIdx.x < 2) {
        float acc = lin_b[threadIdx.x];
        for (int c = 0; c < HL + 1; c++)
            acc = fmaf(sd[c], lin_w[c * 2 + threadIdx.x], acc);
        out[g * 2 + threadIdx.x] = acc;
    }
}

// ---------------- launch ----------------
extern "C" void kernel_launch(void* const* d_in, const int* in_sizes, int n_in,
                              void* d_out, int out_size)
{
    const float* x      = (const float*)d_in[0];
    const void*  ei     = d_in[1];
    const void*  batch  = d_in[2];
    const float* w1_0   = (const float*)d_in[3];
    const float* w1_rest= (const float*)d_in[4];
    const float* b1     = (const float*)d_in[5];
    const float* gm     = (const float*)d_in[6];
    const float* bm     = (const float*)d_in[7];
    const float* w2     = (const float*)d_in[8];
    const float* b2     = (const float*)d_in[9];
    const float* go     = (const float*)d_in[10];
    const float* bo     = (const float*)d_in[11];
    const float* lin_w  = (const float*)d_in[12];
    const float* lin_b  = (const float*)d_in[13];
    float* out = (float*)d_out;

    int N = in_sizes[0];
    int E = in_sizes[1] / 2;
    float invN = 1.f / (float)N;

    int nb256 = (N + 255) / 256;
    int eb256 = (E + 255) / 256;
    int gemmGrid = (N + 63) / 64;

    detect_kernel<<<1, 256>>>(ei, batch, in_sizes[2]);
    zero_kernel<<<nb256, 256>>>(N);
    hist_kernel<<<eb256, 256>>>(ei, E);
    scan1_kernel<<<nb256, 256>>>(N);
    scan2_kernel<<<1, 256>>>(nb256);
    scan3_kernel<<<nb256, 256>>>(N, E);
    fill_kernel<<<eb256, 256>>>(ei, E);
    starts_kernel<<<nb256, 256>>>(batch, N);

    // layer 0
    l0_kernel<<<gemmGrid, 256>>>(x, w1_0, b1, N);
    gemm2_kernel<<<gemmGrid, 256>>>(0, w2, b2, gm, bm, N, invN);

    // layers 1..4
    for (int l = 1; l < LAY; l++) {
        gemm1agg_kernel<<<gemmGrid, 256>>>(l, w1_rest + (size_t)(l - 1) * HID * HID,
                                           b1 + l * HID, go, bo, N, invN);
        gemm2_kernel<<<gemmGrid, 256>>>(l, w2 + (size_t)l * HID * HID, b2 + l * HID,
                                        gm, bm, N, invN);
    }

    pool_kernel<<<GNUM, 256>>>(x, lin_w, lin_b, go, bo, out, invN);
}

// round 5
// speedup vs baseline: 1.2326x; 1.2326x over previous
#include <cuda_runtime.h>
#include <cstdint>

#define NMAX 50000
#define EMAX 800000
#define GNUM 512
#define HID 64
#define LAY 5
#define HL 320
#define BN_EPS 1e-5f

// ---------------- static scratch ----------------
__device__ float g_agg [(size_t)NMAX * HID];   // BN'd (h + sum_j h_j) per layer
__device__ float g_z   [(size_t)NMAX * HID];
__device__ float g_outs[(size_t)NMAX * HL];    // RAW gemm2 outputs (pre-BN), layer l at col l*64
__device__ float g_stats[LAY * 256];           // per layer: sum(z),sq(z),sum(v),sq(v)
__device__ int   g_is64_e, g_is64_b;
// CSR
__device__ int   g_deg[NMAX];
__device__ int   g_rowptr[NMAX + 1];
__device__ int   g_cur[NMAX];
__device__ int   g_part[256];
__device__ int   g_partscan[256];
__device__ int   g_csrc[EMAX];

__device__ __forceinline__ long ldidx(const void* p, long i, int is64) {
    return is64 ? (long)((const long long*)p)[i] : (long)((const int*)p)[i];
}

// ---------------- dtype detection ----------------
__global__ void detect_kernel(const void* ei, const void* batch, int ncount) {
    __shared__ int flag;
    const int* p = (const int*)ei;
    if (threadIdx.x == 0) flag = 0;
    __syncthreads();
    for (int i = threadIdx.x; i < 4096; i += blockDim.x)
        if (p[2 * i + 1] != 0) atomicOr(&flag, 1);
    __syncthreads();
    if (threadIdx.x == 0) { g_is64_e = (flag == 0); flag = 0; }
    __syncthreads();
    const int* q = (const int*)batch;
    int half = ncount / 2;
    for (int i = threadIdx.x; i < 2048; i += blockDim.x) {
        int pos = half - 1 - i;
        if (pos >= 0 && q[2 * pos + 1] != 0) atomicOr(&flag, 1);
    }
    __syncthreads();
    if (threadIdx.x == 0) g_is64_b = (flag == 0);
}

// ---------------- CSR build ----------------
__global__ void zero_kernel(int n) {
    int i = blockIdx.x * blockDim.x + threadIdx.x;
    if (i < n) g_deg[i] = 0;
    if (i < LAY * 256) g_stats[i] = 0.f;
}

__global__ void hist_kernel(const void* __restrict__ ei, int E) {
    int e = blockIdx.x * blockDim.x + threadIdx.x;
    if (e >= E) return;
    int dst = (int)ldidx(ei, (long)E + e, g_is64_e);
    atomicAdd(&g_deg[dst], 1);
}

__global__ void scan1_kernel(int n) {
    __shared__ int sh[256];
    int i = blockIdx.x * 256 + threadIdx.x;
    int v = (i < n) ? g_deg[i] : 0;
    sh[threadIdx.x] = v;
    __syncthreads();
    for (int off = 128; off > 0; off >>= 1) {
        if (threadIdx.x < off) sh[threadIdx.x] += sh[threadIdx.x + off];
        __syncthreads();
    }
    if (threadIdx.x == 0) g_part[blockIdx.x] = sh[0];
}

__global__ void scan2_kernel(int nblocks) {
    __shared__ int sh[256];
    int t = threadIdx.x;
    int v = (t < nblocks) ? g_part[t] : 0;
    sh[t] = v;
    __syncthreads();
    for (int off = 1; off < 256; off <<= 1) {
        int x = (t >= off) ? sh[t - off] : 0;
        __syncthreads();
        sh[t] += x;
        __syncthreads();
    }
    if (t < nblocks) g_partscan[t] = sh[t] - v;
}

__global__ void scan3_kernel(int n, int E) {
    __shared__ int sh[256];
    int t = threadIdx.x;
    int i = blockIdx.x * 256 + t;
    int v = (i < n) ? g_deg[i] : 0;
    sh[t] = v;
    __syncthreads();
    for (int off = 1; off < 256; off <<= 1) {
        int x = (t >= off) ? sh[t - off] : 0;
        __syncthreads();
        sh[t] += x;
        __syncthreads();
    }
    if (i < n) {
        int rp = g_partscan[blockIdx.x] + sh[t] - v;
        g_rowptr[i] = rp;
        g_cur[i] = rp;
        if (i == n - 1) g_rowptr[n] = E;
    }
}

__global__ void fill_kernel(const void* __restrict__ ei, int E) {
    int e = blockIdx.x * blockDim.x + threadIdx.x;
    if (e >= E) return;
    int is64 = g_is64_e;
    int src = (int)ldidx(ei, e, is64);
    int dst = (int)ldidx(ei, (long)E + e, is64);
    int pos = atomicAdd(&g_cur[dst], 1);
    g_csrc[pos] = src;
}

// ---------------- layer 0: fused agg + outer-product GEMM + stats ----------------
__global__ __launch_bounds__(256) void l0_kernel(
    const float* __restrict__ x, const float* __restrict__ w,
    const float* __restrict__ bias, int n)
{
    __shared__ float s_x[64];
    int t = threadIdx.x;
    int lane = t & 31, warp = t >> 5;
    int r0 = blockIdx.x * 64;

    for (int rr = 0; rr < 8; rr++) {
        int rl = warp * 8 + rr;
        int row = r0 + rl;
        float acc = 0.f;
        if (row < n) {
            int beg = g_rowptr[row], end = g_rowptr[row + 1];
            for (int base = beg + lane; base < end; base += 32)
                acc += x[g_csrc[base]];
        }
        #pragma unroll
        for (int o = 16; o > 0; o >>= 1)
            acc += __shfl_xor_sync(0xFFFFFFFFu, acc, o);
        if (lane == 0)
            s_x[rl] = (row < n) ? (acc + x[row]) : 0.f;
    }
    __syncthreads();

    int c = t & 63, g = t >> 6;
    float wc = w[c], bc = bias[c];
    float s = 0.f, q = 0.f;
    int i0 = g * 16;
    #pragma unroll
    for (int i = 0; i < 16; i++) {
        int row = r0 + i0 + i;
        if (row < n) {
            float zv = s_x[i0 + i] * wc + bc;
            g_z[(size_t)row * HID + c] = zv;
            s += zv; q += zv * zv;
        }
    }
    atomicAdd(&g_stats[c], s);
    atomicAdd(&g_stats[64 + c], q);
}

// ---------------- aggregation with inline BN (R2 gather shape) ----------------
// warp per node; lanes split even/odd neighbors; c4 = channel quad.
// g_agg[node] = relu(BN(h_node)) + sum_j relu(BN(h_j))   (complete GIN input)
__global__ __launch_bounds__(256) void aggbn_kernel(
    int l, const float* __restrict__ go, const float* __restrict__ bo,
    int n, float invN)
{
    __shared__ __align__(16) float s_a[64];
    __shared__ __align__(16) float s_b[64];
    int t = threadIdx.x;
    int pc = (l - 1) * HID;
    int pso = (l - 1) * 256 + 128;
    if (t < 64) {
        float mean = g_stats[pso + t] * invN;
        float var  = g_stats[pso + 64 + t] * invN - mean * mean;
        float a = go[pc + t] * rsqrtf(var + BN_EPS);
        s_a[t] = a;
        s_b[t] = bo[pc + t] - mean * a;
    }
    __syncthreads();

    int node = blockIdx.x * 8 + (t >> 5);
    if (node >= n) return;
    int lane = t & 31;
    int half = lane >> 4;
    int c4   = lane & 15;
    float4 ca = *(const float4*)&s_a[c4 * 4];
    float4 cb = *(const float4*)&s_b[c4 * 4];

    int beg = g_rowptr[node], end = g_rowptr[node + 1];
    float4 acc = make_float4(0.f, 0.f, 0.f, 0.f);
    for (int j = beg + half; j < end; j += 2) {
        int src = g_csrc[j];
        float4 v = *(const float4*)(g_outs + (size_t)src * HL + pc + c4 * 4);
        acc.x += fmaxf(fmaf(v.x, ca.x, cb.x), 0.f);
        acc.y += fmaxf(fmaf(v.y, ca.y, cb.y), 0.f);
        acc.z += fmaxf(fmaf(v.z, ca.z, cb.z), 0.f);
        acc.w += fmaxf(fmaf(v.w, ca.w, cb.w), 0.f);
    }
    acc.x += __shfl_xor_sync(0xFFFFFFFFu, acc.x, 16);
    acc.y += __shfl_xor_sync(0xFFFFFFFFu, acc.y, 16);
    acc.z += __shfl_xor_sync(0xFFFFFFFFu, acc.z, 16);
    acc.w += __shfl_xor_sync(0xFFFFFFFFu, acc.w, 16);
    if (half == 0) {
        float4 hv = *(const float4*)(g_outs + (size_t)node * HL + pc + c4 * 4);
        acc.x += fmaxf(fmaf(hv.x, ca.x, cb.x), 0.f);
        acc.y += fmaxf(fmaf(hv.y, ca.y, cb.y), 0.f);
        acc.z += fmaxf(fmaf(hv.z, ca.z, cb.z), 0.f);
        acc.w += fmaxf(fmaf(hv.w, ca.w, cb.w), 0.f);
        *(float4*)(g_agg + (size_t)node * HID + c4 * 4) = acc;
    }
}

// ---------------- gemm1 (layers 1..4): plain GEMM on g_agg + stats ----------------
__global__ __launch_bounds__(256) void gemm1_kernel(
    int l, const float* __restrict__ w, const float* __restrict__ bias, int n)
{
    __shared__ float s_in[64][65];
    __shared__ float s_w[64][64];
    int t = threadIdx.x;
    int r0 = blockIdx.x * 64;
    for (int idx = t; idx < 4096; idx += 256)
        s_w[idx >> 6][idx & 63] = w[idx];
    for (int idx = t; idx < 1024; idx += 256) {
        int r = idx >> 4, k4 = idx & 15;
        int gr = r0 + r;
        float4 val = make_float4(0.f, 0.f, 0.f, 0.f);
        if (gr < n)
            val = *(const float4*)(g_agg + (size_t)gr * HID + k4 * 4);
        s_in[r][k4*4+0] = val.x;
        s_in[r][k4*4+1] = val.y;
        s_in[r][k4*4+2] = val.z;
        s_in[r][k4*4+3] = val.w;
    }
    __syncthreads();

    int r = t & 63, cg = t >> 6, c0 = cg * 16;
    float acc[16];
    #pragma unroll
    for (int j = 0; j < 16; j++) acc[j] = bias[c0 + j];
    #pragma unroll
    for (int k = 0; k < 64; k++) {
        float a = s_in[r][k];
        const float4* wrow = (const float4*)&s_w[k][c0];
        #pragma unroll
        for (int m = 0; m < 4; m++) {
            float4 wv = wrow[m];
            acc[4*m+0] = fmaf(a, wv.x, acc[4*m+0]);
            acc[4*m+1] = fmaf(a, wv.y, acc[4*m+1]);
            acc[4*m+2] = fmaf(a, wv.z, acc[4*m+2]);
            acc[4*m+3] = fmaf(a, wv.w, acc[4*m+3]);
        }
    }
    int gr = r0 + r;
    bool valid = gr < n;
    if (valid) {
        float4* op = (float4*)&g_z[(size_t)gr * HID + c0];
        #pragma unroll
        for (int m = 0; m < 4; m++)
            op[m] = make_float4(acc[4*m], acc[4*m+1], acc[4*m+2], acc[4*m+3]);
    }
    int so = l * 256;
    #pragma unroll
    for (int j = 0; j < 16; j++) {
        float s = valid ? acc[j] : 0.f;
        float q = s * s;
        #pragma unroll
        for (int o = 16; o > 0; o >>= 1) {
            s += __shfl_down_sync(0xFFFFFFFFu, s, o);
            q += __shfl_down_sync(0xFFFFFFFFu, q, o);
        }
        if ((t & 31) == 0) {
            atomicAdd(&g_stats[so + c0 + j], s);
            atomicAdd(&g_stats[so + 64 + c0 + j], q);
        }
    }
}

// ---------------- gemm2: inline coefs + GEMM + stats, raw v -> g_outs ----------------
__global__ __launch_bounds__(256) void gemm2_kernel(
    int l, const float* __restrict__ w, const float* __restrict__ bias,
    const float* __restrict__ gm, const float* __restrict__ bm,
    int n, float invN)
{
    __shared__ float s_in[64][65];
    __shared__ float s_w[64][64];
    __shared__ float s_a[64], s_b[64];
    int t = threadIdx.x;
    int zso = l * 256;

    if (t < 64) {
        float mean = g_stats[zso + t] * invN;
        float var  = g_stats[zso + 64 + t] * invN - mean * mean;
        float a = gm[l * HID + t] * rsqrtf(var + BN_EPS);
        s_a[t] = a;
        s_b[t] = bm[l * HID + t] - mean * a;
    }
    for (int idx = t; idx < 4096; idx += 256)
        s_w[idx >> 6][idx & 63] = w[idx];
    __syncthreads();

    int r0 = blockIdx.x * 64;
    for (int idx = t; idx < 1024; idx += 256) {
        int r = idx >> 4, k4 = idx & 15;
        int gr = r0 + r;
        float4 val = make_float4(0.f, 0.f, 0.f, 0.f);
        if (gr < n) {
            float4 z = *(const float4*)(g_z + (size_t)gr * HID + k4 * 4);
            val.x = fmaxf(fmaf(z.x, s_a[k4*4+0], s_b[k4*4+0]), 0.f);
            val.y = fmaxf(fmaf(z.y, s_a[k4*4+1], s_b[k4*4+1]), 0.f);
            val.z = fmaxf(fmaf(z.z, s_a[k4*4+2], s_b[k4*4+2]), 0.f);
            val.w = fmaxf(fmaf(z.w, s_a[k4*4+3], s_b[k4*4+3]), 0.f);
        }
        s_in[r][k4*4+0] = val.x;
        s_in[r][k4*4+1] = val.y;
        s_in[r][k4*4+2] = val.z;
        s_in[r][k4*4+3] = val.w;
    }
    __syncthreads();

    int r = t & 63, cg = t >> 6, c0 = cg * 16;
    float acc[16];
    #pragma unroll
    for (int j = 0; j < 16; j++) acc[j] = bias[c0 + j];
    #pragma unroll
    for (int k = 0; k < 64; k++) {
        float a = s_in[r][k];
        const float4* wrow = (const float4*)&s_w[k][c0];
        #pragma unroll
        for (int m = 0; m < 4; m++) {
            float4 wv = wrow[m];
            acc[4*m+0] = fmaf(a, wv.x, acc[4*m+0]);
            acc[4*m+1] = fmaf(a, wv.y, acc[4*m+1]);
            acc[4*m+2] = fmaf(a, wv.z, acc[4*m+2]);
            acc[4*m+3] = fmaf(a, wv.w, acc[4*m+3]);
        }
    }
    int gr = r0 + r;
    bool valid = gr < n;
    if (valid) {
        float4* op = (float4*)(g_outs + (size_t)gr * HL + l * HID + c0);
        #pragma unroll
        for (int m = 0; m < 4; m++)
            op[m] = make_float4(acc[4*m], acc[4*m+1], acc[4*m+2], acc[4*m+3]);
    }
    int vso = l * 256 + 128;
    #pragma unroll
    for (int j = 0; j < 16; j++) {
        float s = valid ? acc[j] : 0.f;
        float q = s * s;
        #pragma unroll
        for (int o = 16; o > 0; o >>= 1) {
            s += __shfl_down_sync(0xFFFFFFFFu, s, o);
            q += __shfl_down_sync(0xFFFFFFFFu, q, o);
        }
        if ((t & 31) == 0) {
            atomicAdd(&g_stats[vso + c0 + j], s);
            atomicAdd(&g_stats[vso + 64 + c0 + j], q);
        }
    }
}

// ---------------- pooling (binary-search segments, inline BN, classify) ------------
__global__ void pool_kernel(const float* __restrict__ x, const float* __restrict__ lin_w,
                            const float* __restrict__ lin_b,
                            const float* __restrict__ go, const float* __restrict__ bo,
                            const void* __restrict__ batch,
                            float* __restrict__ out, float invN, int n)
{
    __shared__ float s_a[HL], s_b[HL];
    __shared__ float sd[HL + 1];
    __shared__ int s_se[2];
    int g = blockIdx.x;
    int t = threadIdx.x;
    for (int c = t; c < HL; c += blockDim.x) {
        int l = c >> 6, ch = c & 63;
        int vso = l * 256 + 128;
        float mean = g_stats[vso + ch] * invN;
        float var  = g_stats[vso + 64 + ch] * invN - mean * mean;
        float a = go[c] * rsqrtf(var + BN_EPS);
        s_a[c] = a;
        s_b[c] = bo[c] - mean * a;
    }
    if (t < 2) {
        // lower_bound of (g + t) in sorted batch
        int key = g + t;
        int lo = 0, hi = n;
        int is64 = g_is64_b;
        while (lo < hi) {
            int mid = (lo + hi) >> 1;
            if ((int)ldidx(batch, mid, is64) < key) lo = mid + 1;
            else hi = mid;
        }
        s_se[t] = lo;
    }
    __syncthreads();
    int s = s_se[0], e = s_se[1];
    for (int c = t; c < HL + 1; c += blockDim.x) {
        float acc = 0.f;
        if (c == 0) {
            for (int r = s; r < e; r++) acc += x[r];
        } else {
            float a = s_a[c - 1], b = s_b[c - 1];
            for (int r = s; r < e; r++)
                acc += fmaxf(fmaf(g_outs[(size_t)r * HL + (c - 1)], a, b), 0.f);
        }
        sd[c] = acc;
    }
    __syncthreads();
    if (t < 2) {
        float acc = lin_b[t];
        for (int c = 0; c < HL + 1; c++)
            acc = fmaf(sd[c], lin_w[c * 2 + t], acc);
        out[g * 2 + t] = acc;
    }
}

// ---------------- launch ----------------
extern "C" void kernel_launch(void* const* d_in, const int* in_sizes, int n_in,
                              void* d_out, int out_size)
{
    const float* x      = (const float*)d_in[0];
    const void*  ei     = d_in[1];
    const void*  batch  = d_in[2];
    const float* w1_0   = (const float*)d_in[3];
    const float* w1_rest= (const float*)d_in[4];
    const float* b1     = (const float*)d_in[5];
    const float* gm     = (const float*)d_in[6];
    const float* bm     = (const float*)d_in[7];
    const float* w2     = (const float*)d_in[8];
    const float* b2     = (const float*)d_in[9];
    const float* go     = (const float*)d_in[10];
    const float* bo     = (const float*)d_in[11];
    const float* lin_w  = (const float*)d_in[12];
    const float* lin_b  = (const float*)d_in[13];
    float* out = (float*)d_out;

    int N = in_sizes[0];
    int E = in_sizes[1] / 2;
    float invN = 1.f / (float)N;

    int nb256 = (N + 255) / 256;
    int eb256 = (E + 255) / 256;
    int gemmGrid = (N + 63) / 64;
    int aggGrid  = (N + 7) / 8;

    detect_kernel<<<1, 256>>>(ei, batch, in_sizes[2]);
    zero_kernel<<<nb256, 256>>>(N);
    hist_kernel<<<eb256, 256>>>(ei, E);
    scan1_kernel<<<nb256, 256>>>(N);
    scan2_kernel<<<1, 256>>>(nb256);
    scan3_kernel<<<nb256, 256>>>(N, E);
    fill_kernel<<<eb256, 256>>>(ei, E);

    // layer 0
    l0_kernel<<<gemmGrid, 256>>>(x, w1_0, b1, N);
    gemm2_kernel<<<gemmGrid, 256>>>(0, w2, b2, gm, bm, N, invN);

    // layers 1..4
    for (int l = 1; l < LAY; l++) {
        aggbn_kernel<<<aggGrid, 256>>>(l, go, bo, N, invN);
        gemm1_kernel<<<gemmGrid, 256>>>(l, w1_rest + (size_t)(l - 1) * HID * HID,
                                        b1 + l * HID, N);
        gemm2_kernel<<<gemmGrid, 256>>>(l, w2 + (size_t)l * HID * HID, b2 + l * HID,
                                        gm, bm, N, invN);
    }

    pool_kernel<<<GNUM, 256>>>(x, lin_w, lin_b, go, bo, batch, out, invN, N);
}

// round 7
// speedup vs baseline: 1.3188x; 1.0700x over previous
#include <cuda_runtime.h>
#include <cstdint>

#define NMAX 50000
#define EMAX 800000
#define GNUM 512
#define HID 64
#define LAY 5
#define HL 320
#define BN_EPS 1e-5f
#define PB 592          // persistent blocks: 4/SM on 148 SMs (GB300 has 152)

// ---------------- static scratch ----------------
__device__ float g_z   [(size_t)NMAX * HID];
__device__ float g_outs[(size_t)NMAX * HL];   // RAW gemm2 outputs per layer
__device__ float g_stats[LAY * 256];          // per layer: sum(z),sq(z),sum(v),sq(v)
__device__ int   g_deg[NMAX];
__device__ int   g_rowptr[NMAX + 1];
__device__ int   g_cur[NMAX];
__device__ int   g_part[256];
__device__ int   g_partscan[256];
__device__ int   g_csrc[EMAX];
__device__ int   g_is64_e, g_is64_b;
__device__ unsigned g_count = 0, g_epoch = 0;

__device__ __forceinline__ long ldidx(const void* p, long i, int is64) {
    return is64 ? (long)((const long long*)p)[i] : (long)((const int*)p)[i];
}

// volatile epoch load the compiler cannot CSE/hoist/delete
__device__ __forceinline__ unsigned ld_epoch() {
    unsigned v;
    asm volatile("ld.global.cg.u32 %0, [%1];" : "=r"(v) : "l"(&g_epoch) : "memory");
    return v;
}

// ---------------- grid-wide barrier (epoch based; replay-safe) ----------------
__device__ __forceinline__ void gbar() {
    __syncthreads();
    if (threadIdx.x == 0) {
        __threadfence();
        unsigned e = ld_epoch();
        if (atomicAdd(&g_count, 1) == gridDim.x - 1) {
            atomicExch(&g_count, 0u);
            __threadfence();
            atomicExch(&g_epoch, e + 1);
        } else {
            unsigned cur;
            do {
                __nanosleep(20);
                cur = ld_epoch();
            } while (cur == e);
        }
        __threadfence();
    }
    __syncthreads();
}

// ---------------- shared memory union ----------------
struct SmGemm {
    float w[64][64];
    float in[64][65];
    float a[64];
    float b[64];
};
struct SmPool {
    float a[HL];
    float b[HL];
    float sd[HL + 1];
    int   se[2];
};
struct SmScan { int sh[257]; };
struct SmL0   { float xr[64]; };
union __align__(16) SmU {
    SmGemm g;
    SmPool p;
    SmScan s;
    SmL0   l0;
};

// ---------------- the whole network in one kernel ----------------
__global__ void __launch_bounds__(256, 4) fused_all(
    const float* __restrict__ x, const void* __restrict__ ei,
    const void* __restrict__ batch,
    const float* __restrict__ w1_0, const float* __restrict__ w1_rest,
    const float* __restrict__ b1,
    const float* __restrict__ gm, const float* __restrict__ bm,
    const float* __restrict__ w2, const float* __restrict__ b2,
    const float* __restrict__ go, const float* __restrict__ bo,
    const float* __restrict__ lin_w, const float* __restrict__ lin_b,
    float* __restrict__ out, int n, int E, int bcount, float invN)
{
    __shared__ SmU sm;
    int t = threadIdx.x, b = blockIdx.x, nb = gridDim.x;
    int lane = t & 31, warp = t >> 5;
    long gstride = (long)nb * 256;

    // ---------- P0: zero deg/stats + dtype detect ----------
    for (long i = (long)b * 256 + t; i < n; i += gstride) g_deg[i] = 0;
    if (b == 0)
        for (int i = t; i < LAY * 256; i += 256) g_stats[i] = 0.f;
    if (b == 1) {
        const int* p = (const int*)ei;
        int f = 0;
        for (int i = t; i < 4096; i += 256) if (p[2 * i + 1] != 0) f = 1;
        f = __syncthreads_or(f);
        if (t == 0) g_is64_e = (f == 0);
        const int* q = (const int*)batch;
        int hf = bcount / 2;
        int f2 = 0;
        for (int i = t; i < 2048; i += 256) {
            int pos = hf - 1 - i;
            if (pos >= 0 && q[2 * pos + 1] != 0) f2 = 1;
        }
        f2 = __syncthreads_or(f2);
        if (t == 0) g_is64_b = (f2 == 0);
    }
    gbar();                                                   // 1

    // ---------- P1: degree histogram ----------
    {
        int is64 = g_is64_e;
        for (long e0 = (long)b * 256 + t; e0 < E; e0 += gstride) {
            int dst = (int)ldidx(ei, (long)E + e0, is64);
            atomicAdd(&g_deg[dst], 1);
        }
    }
    gbar();                                                   // 2

    int nch = (n + 255) / 256;

    // ---------- P2: chunk sums ----------
    for (int c = b; c < nch; c += nb) {
        int i = c * 256 + t;
        sm.s.sh[t] = (i < n) ? g_deg[i] : 0;
        __syncthreads();
        for (int off = 128; off > 0; off >>= 1) {
            if (t < off) sm.s.sh[t] += sm.s.sh[t + off];
            __syncthreads();
        }
        if (t == 0) g_part[c] = sm.s.sh[0];
        __syncthreads();
    }
    gbar();                                                   // 3

    // ---------- P3: scan of chunk sums (block 0) ----------
    if (b == 0) {
        int v = (t < nch) ? g_part[t] : 0;
        sm.s.sh[t] = v;
        __syncthreads();
        for (int off = 1; off < 256; off <<= 1) {
            int xv = (t >= off) ? sm.s.sh[t - off] : 0;
            __syncthreads();
            sm.s.sh[t] += xv;
            __syncthreads();
        }
        if (t < nch) g_partscan[t] = sm.s.sh[t] - v;
    }
    gbar();                                                   // 4

    // ---------- P4: rowptr ----------
    for (int c = b; c < nch; c += nb) {
        int i = c * 256 + t;
        int v = (i < n) ? g_deg[i] : 0;
        sm.s.sh[t] = v;
        __syncthreads();
        for (int off = 1; off < 256; off <<= 1) {
            int xv = (t >= off) ? sm.s.sh[t - off] : 0;
            __syncthreads();
            sm.s.sh[t] += xv;
            __syncthreads();
        }
        if (i < n) {
            int rp = g_partscan[c] + sm.s.sh[t] - v;
            g_rowptr[i] = rp;
            g_cur[i] = rp;
            if (i == n - 1) g_rowptr[n] = E;
        }
        __syncthreads();
    }
    gbar();                                                   // 5

    // ---------- P5: fill CSR ----------
    {
        int is64 = g_is64_e;
        for (long e0 = (long)b * 256 + t; e0 < E; e0 += gstride) {
            int src = (int)ldidx(ei, e0, is64);
            int dst = (int)ldidx(ei, (long)E + e0, is64);
            int pos = atomicAdd(&g_cur[dst], 1);
            g_csrc[pos] = src;
        }
    }
    gbar();                                                   // 6

    int ntiles = (n + 63) / 64;

    // ---------- P6: layer-0 agg + outer-product z + stats ----------
    for (int tile = b; tile < ntiles; tile += nb) {
        int r0 = tile * 64;
        for (int rr = 0; rr < 8; rr++) {
            int rl = warp * 8 + rr;
            int row = r0 + rl;
            float acc = 0.f;
            if (row < n) {
                int beg = g_rowptr[row], end = g_rowptr[row + 1];
                for (int j = beg + lane; j < end; j += 32)
                    acc += x[g_csrc[j]];
            }
            #pragma unroll
            for (int o = 16; o > 0; o >>= 1)
                acc += __shfl_xor_sync(0xFFFFFFFFu, acc, o);
            if (lane == 0)
                sm.l0.xr[rl] = (row < n) ? (acc + x[row]) : 0.f;
        }
        __syncthreads();
        int c = t & 63, g4 = t >> 6;
        float wc = w1_0[c], bc = b1[c];
        float s = 0.f, q = 0.f;
        #pragma unroll
        for (int i = 0; i < 16; i++) {
            int row = r0 + g4 * 16 + i;
            if (row < n) {
                float zv = sm.l0.xr[g4 * 16 + i] * wc + bc;
                g_z[(size_t)row * HID + c] = zv;
                s += zv; q += zv * zv;
            }
        }
        atomicAdd(&g_stats[c], s);
        atomicAdd(&g_stats[64 + c], q);
        __syncthreads();
    }
    gbar();                                                   // 7

    // ---------- layers ----------
    for (int l = 0; l < LAY; l++) {
        // ----- gemm1 + fused gather (l >= 1) -----
        if (l > 0) {
            int pc = (l - 1) * HID;
            int pso = (l - 1) * 256 + 128;
            if (t < 64) {
                float mean = g_stats[pso + t] * invN;
                float var  = g_stats[pso + 64 + t] * invN - mean * mean;
                float a = go[pc + t] * rsqrtf(var + BN_EPS);
                sm.g.a[t] = a;
                sm.g.b[t] = bo[pc + t] - mean * a;
            }
            const float* w = w1_rest + (size_t)(l - 1) * 4096;
            for (int idx = t; idx < 4096; idx += 256)
                sm.g.w[idx >> 6][idx & 63] = w[idx];
            __syncthreads();

            int half = lane >> 4, c4 = lane & 15;
            float4 ca = *(const float4*)&sm.g.a[c4 * 4];
            float4 cb = *(const float4*)&sm.g.b[c4 * 4];
            const float* bias = b1 + l * HID;
            int so = l * 256;

            for (int tile = b; tile < ntiles; tile += nb) {
                int r0 = tile * 64;
                for (int rr = 0; rr < 8; rr++) {
                    int rl = warp * 8 + rr;
                    int row = r0 + rl;
                    float4 acc = make_float4(0.f, 0.f, 0.f, 0.f);
                    if (row < n) {
                        int beg = g_rowptr[row], end = g_rowptr[row + 1];
                        for (int j = beg + half; j < end; j += 2) {
                            int src = g_csrc[j];
                            float4 v = *(const float4*)(g_outs + (size_t)src * HL + pc + c4 * 4);
                            acc.x += fmaxf(fmaf(v.x, ca.x, cb.x), 0.f);
                            acc.y += fmaxf(fmaf(v.y, ca.y, cb.y), 0.f);
                            acc.z += fmaxf(fmaf(v.z, ca.z, cb.z), 0.f);
                            acc.w += fmaxf(fmaf(v.w, ca.w, cb.w), 0.f);
                        }
                    }
                    acc.x += __shfl_xor_sync(0xFFFFFFFFu, acc.x, 16);
                    acc.y += __shfl_xor_sync(0xFFFFFFFFu, acc.y, 16);
                    acc.z += __shfl_xor_sync(0xFFFFFFFFu, acc.z, 16);
                    acc.w += __shfl_xor_sync(0xFFFFFFFFu, acc.w, 16);
                    if (half == 0) {
                        if (row < n) {
                            float4 hv = *(const float4*)(g_outs + (size_t)row * HL + pc + c4 * 4);
                            acc.x += fmaxf(fmaf(hv.x, ca.x, cb.x), 0.f);
                            acc.y += fmaxf(fmaf(hv.y, ca.y, cb.y), 0.f);
                            acc.z += fmaxf(fmaf(hv.z, ca.z, cb.z), 0.f);
                            acc.w += fmaxf(fmaf(hv.w, ca.w, cb.w), 0.f);
                        }
                        sm.g.in[rl][c4 * 4 + 0] = acc.x;
                        sm.g.in[rl][c4 * 4 + 1] = acc.y;
                        sm.g.in[rl][c4 * 4 + 2] = acc.z;
                        sm.g.in[rl][c4 * 4 + 3] = acc.w;
                    }
                }
                __syncthreads();
                int r = t & 63, c0 = (t >> 6) * 16;
                float acc[16];
                #pragma unroll
                for (int j = 0; j < 16; j++) acc[j] = bias[c0 + j];
                #pragma unroll
                for (int k = 0; k < 64; k++) {
                    float a = sm.g.in[r][k];
                    const float4* wrow = (const float4*)&sm.g.w[k][c0];
                    #pragma unroll
                    for (int m = 0; m < 4; m++) {
                        float4 wv = wrow[m];
                        acc[4*m+0] = fmaf(a, wv.x, acc[4*m+0]);
                        acc[4*m+1] = fmaf(a, wv.y, acc[4*m+1]);
                        acc[4*m+2] = fmaf(a, wv.z, acc[4*m+2]);
                        acc[4*m+3] = fmaf(a, wv.w, acc[4*m+3]);
                    }
                }
                int gr = r0 + r;
                bool valid = gr < n;
                if (valid) {
                    float4* op = (float4*)&g_z[(size_t)gr * HID + c0];
                    #pragma unroll
                    for (int m = 0; m < 4; m++)
                        op[m] = make_float4(acc[4*m], acc[4*m+1], acc[4*m+2], acc[4*m+3]);
                }
                #pragma unroll
                for (int j = 0; j < 16; j++) {
                    float s = valid ? acc[j] : 0.f;
                    float q = s * s;
                    #pragma unroll
                    for (int o = 16; o > 0; o >>= 1) {
                        s += __shfl_down_sync(0xFFFFFFFFu, s, o);
                        q += __shfl_down_sync(0xFFFFFFFFu, q, o);
                    }
                    if (lane == 0) {
                        atomicAdd(&g_stats[so + c0 + j], s);
                        atomicAdd(&g_stats[so + 64 + c0 + j], q);
                    }
                }
                __syncthreads();
            }
            gbar();                                           // per layer (A)
        }

        // ----- gemm2 -----
        {
            int zso = l * 256;
            if (t < 64) {
                float mean = g_stats[zso + t] * invN;
                float var  = g_stats[zso + 64 + t] * invN - mean * mean;
                float a = gm[l * HID + t] * rsqrtf(var + BN_EPS);
                sm.g.a[t] = a;
                sm.g.b[t] = bm[l * HID + t] - mean * a;
            }
            const float* w = w2 + (size_t)l * 4096;
            for (int idx = t; idx < 4096; idx += 256)
                sm.g.w[idx >> 6][idx & 63] = w[idx];
            __syncthreads();

            const float* bias = b2 + l * HID;
            int vso = l * 256 + 128;

            for (int tile = b; tile < ntiles; tile += nb) {
                int r0 = tile * 64;
                for (int idx = t; idx < 1024; idx += 256) {
                    int r = idx >> 4, k4 = idx & 15;
                    int gr = r0 + r;
                    float4 val = make_float4(0.f, 0.f, 0.f, 0.f);
                    if (gr < n) {
                        float4 z = *(const float4*)(g_z + (size_t)gr * HID + k4 * 4);
                        val.x = fmaxf(fmaf(z.x, sm.g.a[k4*4+0], sm.g.b[k4*4+0]), 0.f);
                        val.y = fmaxf(fmaf(z.y, sm.g.a[k4*4+1], sm.g.b[k4*4+1]), 0.f);
                        val.z = fmaxf(fmaf(z.z, sm.g.a[k4*4+2], sm.g.b[k4*4+2]), 0.f);
                        val.w = fmaxf(fmaf(z.w, sm.g.a[k4*4+3], sm.g.b[k4*4+3]), 0.f);
                    }
                    sm.g.in[r][k4*4+0] = val.x;
                    sm.g.in[r][k4*4+1] = val.y;
                    sm.g.in[r][k4*4+2] = val.z;
                    sm.g.in[r][k4*4+3] = val.w;
                }
                __syncthreads();
                int r = t & 63, c0 = (t >> 6) * 16;
                float acc[16];
                #pragma unroll
                for (int j = 0; j < 16; j++) acc[j] = bias[c0 + j];
                #pragma unroll
                for (int k = 0; k < 64; k++) {
                    float a = sm.g.in[r][k];
                    const float4* wrow = (const float4*)&sm.g.w[k][c0];
                    #pragma unroll
                    for (int m = 0; m < 4; m++) {
                        float4 wv = wrow[m];
                        acc[4*m+0] = fmaf(a, wv.x, acc[4*m+0]);
                        acc[4*m+1] = fmaf(a, wv.y, acc[4*m+1]);
                        acc[4*m+2] = fmaf(a, wv.z, acc[4*m+2]);
                        acc[4*m+3] = fmaf(a, wv.w, acc[4*m+3]);
                    }
                }
                int gr = r0 + r;
                bool valid = gr < n;
                if (valid) {
                    float4* op = (float4*)(g_outs + (size_t)gr * HL + l * HID + c0);
                    #pragma unroll
                    for (int m = 0; m < 4; m++)
                        op[m] = make_float4(acc[4*m], acc[4*m+1], acc[4*m+2], acc[4*m+3]);
                }
                #pragma unroll
                for (int j = 0; j < 16; j++) {
                    float s = valid ? acc[j] : 0.f;
                    float q = s * s;
                    #pragma unroll
                    for (int o = 16; o > 0; o >>= 1) {
                        s += __shfl_down_sync(0xFFFFFFFFu, s, o);
                        q += __shfl_down_sync(0xFFFFFFFFu, q, o);
                    }
                    if (lane == 0) {
                        atomicAdd(&g_stats[vso + c0 + j], s);
                        atomicAdd(&g_stats[vso + 64 + c0 + j], q);
                    }
                }
                __syncthreads();
            }
            gbar();                                           // per layer (B)
        }
    }

    // ---------- pool + classifier ----------
    for (int c = t; c < HL; c += 256) {
        int l = c >> 6, ch = c & 63;
        int vso = l * 256 + 128;
        float mean = g_stats[vso + ch] * invN;
        float var  = g_stats[vso + 64 + ch] * invN - mean * mean;
        float a = go[c] * rsqrtf(var + BN_EPS);
        sm.p.a[c] = a;
        sm.p.b[c] = bo[c] - mean * a;
    }
    __syncthreads();
    {
        int is64 = g_is64_b;
        for (int g = b; g < GNUM; g += nb) {
            if (t < 2) {
                int key = g + t;
                int lo = 0, hi = n;
                while (lo < hi) {
                    int mid = (lo + hi) >> 1;
                    if ((int)ldidx(batch, mid, is64) < key) lo = mid + 1;
                    else hi = mid;
                }
                sm.p.se[t] = lo;
            }
            __syncthreads();
            int s = sm.p.se[0], e = sm.p.se[1];
            for (int c = t; c < HL + 1; c += 256) {
                float acc = 0.f;
                if (c == 0) {
                    for (int r = s; r < e; r++) acc += x[r];
                } else {
                    float a = sm.p.a[c - 1], bb = sm.p.b[c - 1];
                    for (int r = s; r < e; r++)
                        acc += fmaxf(fmaf(g_outs[(size_t)r * HL + (c - 1)], a, bb), 0.f);
                }
                sm.p.sd[c] = acc;
            }
            __syncthreads();
            if (t < 2) {
                float acc = lin_b[t];
                for (int c = 0; c < HL + 1; c++)
                    acc = fmaf(sm.p.sd[c], lin_w[c * 2 + t], acc);
                out[g * 2 + t] = acc;
            }
            __syncthreads();
        }
    }
}

// ---------------- launch ----------------
extern "C" void kernel_launch(void* const* d_in, const int* in_sizes, int n_in,
                              void* d_out, int out_size)
{
    const float* x      = (const float*)d_in[0];
    const void*  ei     = d_in[1];
    const void*  batch  = d_in[2];
    const float* w1_0   = (const float*)d_in[3];
    const float* w1_rest= (const float*)d_in[4];
    const float* b1     = (const float*)d_in[5];
    const float* gm     = (const float*)d_in[6];
    const float* bm     = (const float*)d_in[7];
    const float* w2     = (const float*)d_in[8];
    const float* b2     = (const float*)d_in[9];
    const float* go     = (const float*)d_in[10];
    const float* bo     = (const float*)d_in[11];
    const float* lin_w  = (const float*)d_in[12];
    const float* lin_b  = (const float*)d_in[13];
    float* out = (float*)d_out;

    int N = in_sizes[0];
    int E = in_sizes[1] / 2;
    float invN = 1.f / (float)N;

    fused_all<<<PB, 256>>>(x, ei, batch, w1_0, w1_rest, b1, gm, bm,
                           w2, b2, go, bo, lin_w, lin_b, out,
                           N, E, in_sizes[2], invN);
}